// round 1
// baseline (speedup 1.0000x reference)
#include <cuda_runtime.h>
#include <math.h>

#define NNODES 40962
#define NEDGES 327680
#define D 512
#define K1 1024
#define MPAD 41088  // 321 * 128, row padding for gemm tiles

// Scratch (device globals: no allocations allowed)
__device__ float g_edge_sum[(size_t)NNODES * D];   // ~84 MB
__device__ float g_h[(size_t)MPAD * D];            // ~84 MB

// ---------------------------------------------------------------------------
// K0: zero the scatter target
// ---------------------------------------------------------------------------
__global__ void zero_kernel() {
    size_t i = (size_t)blockIdx.x * blockDim.x + threadIdx.x;
    size_t n4 = (size_t)NNODES * D / 4;
    if (i < n4) reinterpret_cast<float4*>(g_edge_sum)[i] = make_float4(0.f, 0.f, 0.f, 0.f);
}

// ---------------------------------------------------------------------------
// K1: scatter-add edge_attr rows into g_edge_sum[receiver]
// One block per edge, 128 threads, float4 per thread (512 floats/row).
// Target region (84 MB) fits in L2, so the RMW traffic stays on-die.
// ---------------------------------------------------------------------------
__global__ void scatter_kernel(const float* __restrict__ edge_attr,
                               const int* __restrict__ edge_index) {
    int e = blockIdx.x;
    int t = threadIdx.x;
    int r = __ldg(&edge_index[NEDGES + e]);  // receiver = edge_index[1][e]
    float4 v = *reinterpret_cast<const float4*>(edge_attr + (size_t)e * D + t * 4);
    float* dst = g_edge_sum + (size_t)r * D + t * 4;
    atomicAdd(dst + 0, v.x);
    atomicAdd(dst + 1, v.y);
    atomicAdd(dst + 2, v.z);
    atomicAdd(dst + 3, v.w);
}

// ---------------------------------------------------------------------------
// K2: GEMM1  h = silu([node | edge_sum] @ W1 + b1)
// M=40962 (padded tiles), N=512, K=1024.  BM=128, BN=128, BK=16, 256 thr, 8x8/thr.
// A is read from node for k<512 and g_edge_sum for k>=512 (no concat copy).
// ---------------------------------------------------------------------------
__global__ __launch_bounds__(256) void gemm1_kernel(const float* __restrict__ node,
                                                    const float* __restrict__ W1,
                                                    const float* __restrict__ b1) {
    __shared__ float As[16][128];
    __shared__ float Bs[16][128];

    int tid = threadIdx.x;
    int bx = blockIdx.x;   // over N (4 tiles of 128)
    int by = blockIdx.y;   // over M (321 tiles of 128)
    int ty = tid >> 4;     // 0..15
    int tx = tid & 15;     // 0..15
    int row0 = ty * 8;
    int col0 = tx * 8;

    float acc[8][8] = {};

    for (int kt = 0; kt < K1 / 16; ++kt) {
        // ---- load A tile (128 x 16), transpose into As[k][m]
        const float* srcA = (kt < 32) ? node : g_edge_sum;
        int kbase = (kt < 32) ? kt * 16 : (kt - 32) * 16;
#pragma unroll
        for (int l = 0; l < 2; ++l) {
            int s  = tid * 2 + l;       // 0..511 float4 slots
            int ar = s >> 2;            // tile row 0..127
            int ac = (s & 3) * 4;       // k offset within tile
            int grow = by * 128 + ar;
            float4 v = make_float4(0.f, 0.f, 0.f, 0.f);
            if (grow < NNODES)
                v = *reinterpret_cast<const float4*>(srcA + (size_t)grow * D + kbase + ac);
            As[ac + 0][ar] = v.x;
            As[ac + 1][ar] = v.y;
            As[ac + 2][ar] = v.z;
            As[ac + 3][ar] = v.w;
        }
        // ---- load B tile (16 x 128) from W1 [1024 x 512]
#pragma unroll
        for (int l = 0; l < 2; ++l) {
            int s  = tid * 2 + l;       // 0..511
            int br = s >> 5;            // 0..15
            int bc = (s & 31) * 4;      // 0..124
            float4 v = *reinterpret_cast<const float4*>(
                W1 + (size_t)(kt * 16 + br) * D + bx * 128 + bc);
            *reinterpret_cast<float4*>(&Bs[br][bc]) = v;
        }
        __syncthreads();

#pragma unroll
        for (int kk = 0; kk < 16; ++kk) {
            float a[8], b[8];
#pragma unroll
            for (int i = 0; i < 8; ++i) a[i] = As[kk][row0 + i];
#pragma unroll
            for (int j = 0; j < 8; ++j) b[j] = Bs[kk][col0 + j];
#pragma unroll
            for (int i = 0; i < 8; ++i)
#pragma unroll
                for (int j = 0; j < 8; ++j)
                    acc[i][j] = fmaf(a[i], b[j], acc[i][j]);
        }
        __syncthreads();
    }

    // ---- epilogue: bias + SiLU, write to padded g_h (no guard needed: MPAD rows)
#pragma unroll
    for (int i = 0; i < 8; ++i) {
        int grow = by * 128 + row0 + i;
#pragma unroll
        for (int j = 0; j < 8; j += 4) {
            float4 o;
            float* po = &o.x;
#pragma unroll
            for (int q = 0; q < 4; ++q) {
                int col = bx * 128 + col0 + j + q;
                float v = acc[i][j + q] + __ldg(&b1[col]);
                po[q] = v / (1.0f + expf(-v));   // silu
            }
            *reinterpret_cast<float4*>(&g_h[(size_t)grow * D + bx * 128 + col0 + j]) = o;
        }
    }
}

// ---------------------------------------------------------------------------
// K3: GEMM2 + bias + LayerNorm, fused.
// Each block computes a full 32 x 512 output slab (whole rows -> LN in-block).
// BM=32, BN=512, BK=16, 256 threads (4 x 64), 8x8 per thread.
// ---------------------------------------------------------------------------
__global__ __launch_bounds__(256) void gemm2_ln_kernel(const float* __restrict__ W2,
                                                       const float* __restrict__ b2,
                                                       const float* __restrict__ gamma,
                                                       const float* __restrict__ beta,
                                                       float* __restrict__ out) {
    __shared__ float As[16][32];
    __shared__ float Bs[16][512];   // reused as reduction buffer after mainloop

    int tid = threadIdx.x;
    int bk = blockIdx.x;            // row block (32 rows)
    int ty = tid >> 6;              // 0..3
    int tx = tid & 63;              // 0..63
    int r0 = ty * 8;
    int c0 = tx * 8;

    float acc[8][8] = {};

    for (int kt = 0; kt < D / 16; ++kt) {
        // ---- load A tile (32 x 16) from g_h, transpose
        if (tid < 128) {
            int s  = tid;           // 0..127 float4 slots
            int ar = s >> 2;        // 0..31
            int ac = (s & 3) * 4;   // 0..12
            int grow = bk * 32 + ar;  // < 40992 <= MPAD, always valid
            float4 v = *reinterpret_cast<const float4*>(
                g_h + (size_t)grow * D + kt * 16 + ac);
            As[ac + 0][ar] = v.x;
            As[ac + 1][ar] = v.y;
            As[ac + 2][ar] = v.z;
            As[ac + 3][ar] = v.w;
        }
        // ---- load B tile (16 x 512) from W2 [512 x 512]
#pragma unroll
        for (int l = 0; l < 8; ++l) {
            int s  = tid + l * 256;     // 0..2047 float4 slots
            int br = s >> 7;            // 0..15
            int bc = (s & 127) * 4;     // 0..508
            *reinterpret_cast<float4*>(&Bs[br][bc]) =
                *reinterpret_cast<const float4*>(W2 + (size_t)(kt * 16 + br) * D + bc);
        }
        __syncthreads();

#pragma unroll
        for (int kk = 0; kk < 16; ++kk) {
            float a[8], b[8];
#pragma unroll
            for (int i = 0; i < 8; ++i) a[i] = As[kk][r0 + i];
#pragma unroll
            for (int j = 0; j < 8; ++j) b[j] = Bs[kk][c0 + j];
#pragma unroll
            for (int i = 0; i < 8; ++i)
#pragma unroll
                for (int j = 0; j < 8; ++j)
                    acc[i][j] = fmaf(a[i], b[j], acc[i][j]);
        }
        __syncthreads();
    }

    // ---- add bias, compute per-thread partial row sums
    float bfrag[8];
#pragma unroll
    for (int j = 0; j < 8; ++j) bfrag[j] = __ldg(&b2[c0 + j]);

    float psum[8], psq[8];
#pragma unroll
    for (int i = 0; i < 8; ++i) {
        float s = 0.f, q = 0.f;
#pragma unroll
        for (int j = 0; j < 8; ++j) {
            float v = acc[i][j] + bfrag[j];
            acc[i][j] = v;
            s += v;
            q += v * v;
        }
        psum[i] = s;
        psq[i]  = q;
    }

    // ---- LN reduction across the 64 tx lanes, per row, in (reused) smem
    float* red_sum = &Bs[0][0];          // 32 * 64 floats
    float* red_sq  = red_sum + 32 * 64;  // 32 * 64 floats
    // last __syncthreads of the mainloop guarantees Bs no longer read
#pragma unroll
    for (int i = 0; i < 8; ++i) {
        red_sum[(r0 + i) * 64 + tx] = psum[i];
        red_sq [(r0 + i) * 64 + tx] = psq[i];
    }
    __syncthreads();
    for (int sstep = 32; sstep >= 1; sstep >>= 1) {
        if (tx < sstep) {
#pragma unroll
            for (int i = 0; i < 8; ++i) {
                red_sum[(r0 + i) * 64 + tx] += red_sum[(r0 + i) * 64 + tx + sstep];
                red_sq [(r0 + i) * 64 + tx] += red_sq [(r0 + i) * 64 + tx + sstep];
            }
        }
        __syncthreads();
    }

    // ---- normalize + affine + store
#pragma unroll
    for (int i = 0; i < 8; ++i) {
        int grow = bk * 32 + r0 + i;
        if (grow < NNODES) {
            float mean = red_sum[(r0 + i) * 64] * (1.0f / 512.0f);
            float var  = red_sq [(r0 + i) * 64] * (1.0f / 512.0f) - mean * mean;
            float rstd = rsqrtf(var + 1e-5f);
#pragma unroll
            for (int j = 0; j < 8; j += 4) {
                float4 o;
                float* po = &o.x;
#pragma unroll
                for (int q = 0; q < 4; ++q) {
                    int col = c0 + j + q;
                    po[q] = (acc[i][j + q] - mean) * rstd * __ldg(&gamma[col]) + __ldg(&beta[col]);
                }
                *reinterpret_cast<float4*>(out + (size_t)grow * D + c0 + j) = o;
            }
        }
    }
}

// ---------------------------------------------------------------------------
extern "C" void kernel_launch(void* const* d_in, const int* in_sizes, int n_in,
                              void* d_out, int out_size) {
    const float* node       = (const float*)d_in[0];
    const int*   edge_index = (const int*)  d_in[1];
    const float* edge_attr  = (const float*)d_in[2];
    const float* W1         = (const float*)d_in[3];
    const float* b1         = (const float*)d_in[4];
    const float* W2         = (const float*)d_in[5];
    const float* b2         = (const float*)d_in[6];
    const float* gamma      = (const float*)d_in[7];
    const float* beta       = (const float*)d_in[8];
    float* out = (float*)d_out;

    size_t n4 = (size_t)NNODES * D / 4;
    zero_kernel<<<(unsigned)((n4 + 255) / 256), 256>>>();
    scatter_kernel<<<NEDGES, 128>>>(edge_attr, edge_index);

    dim3 g1(4, (NNODES + 127) / 128);
    gemm1_kernel<<<g1, 256>>>(node, W1, b1);

    gemm2_ln_kernel<<<(NNODES + 31) / 32, 256>>>(W2, b2, gamma, beta, out);
}